// round 7
// baseline (speedup 1.0000x reference)
#include <cuda_runtime.h>

#define B_ 32
#define S_ 4096
#define H_ 1024
#define NSPANS_ 16
#define NCLS_ 25
#define H4_ (H_ / 4)      // 256 float4 per row
#define CHUNK_ 16         // tokens per pool block
#define NCHUNK_ 4         // ceil(63 / CHUNK_)
#define NBLK_ (B_ * NSPANS_ * NCHUNK_)   // 2048
#define NFC1_ 128         // fc1 tiles (32 j-tiles x 4 b-groups)
#define KT_ 32            // K-tile rows in fc1

// Persistent scratch. Zero-initialized at load; the epilogue restores zeros
// at the end of every call, so each invocation sees identical state.
__device__ float g_pooled[B_ * H_];
__device__ float g_logits[B_ * NCLS_];
__device__ unsigned g_cnt1;
__device__ unsigned g_cnt2;

__device__ __forceinline__ void f4add(float4& a, const float4 b) {
    a.x += b.x; a.y += b.y; a.z += b.z; a.w += b.w;
}

// ---------------------------------------------------------------------------
// One fused kernel, small smem (~10.5KB) so the pool phase keeps occupancy.
// grid (NCHUNK, NSPANS, B) = 2048 blocks, 256 threads.
//   Phase 1 (all blocks): pool one 16-token chunk of one span -> atomicAdd.
//   Ticket 1: last NFC1_ finishers continue as fc1 workers (short spin).
//   Phase 2 (128 blocks): fc1 via double-buffered W1(8KB)+p(2KB) smem tiles,
//     then fc2 partial via shuffle + atomicAdd into g_logits.
//   Ticket 2: provably-last block does sigmoid + restores zero state.
// ---------------------------------------------------------------------------
__global__ void __launch_bounds__(256)
fused_kernel(const float* __restrict__ emb,
             const int* __restrict__ spans,
             const float* __restrict__ W1,
             const float* __restrict__ b1,
             const float* __restrict__ W2,
             const float* __restrict__ b2,
             float* __restrict__ out) {
    const int tid = threadIdx.x;
    const int b = blockIdx.z;
    const int n = blockIdx.y;
    const int c = blockIdx.x;

    __shared__ float wt[2][KT_][32];   // 8 KB W1 tiles
    __shared__ float pt[2][8][KT_];    // 2 KB pooled tiles
    __shared__ float s_inv[8];
    __shared__ int ss, se, svalid;
    __shared__ unsigned s_ticket, s_ticket2;

    // ---------------- Phase 1: pool ----------------------------------------
    if (tid == 0) {
        const int* row = spans + b * (NSPANS_ * 2);
        int s = row[2 * n], e = row[2 * n + 1];
        int v = !(s == 0 && e == 0);
        for (int m = 0; m < n && v; m++) {           // torch 'break' semantics
            if (row[2 * m] == 0 && row[2 * m + 1] == 0) v = 0;
        }
        int cs = s + c * CHUNK_;
        int ce = cs + CHUNK_ < e ? cs + CHUNK_ : e;
        ss = cs; se = ce; svalid = v && (cs < e);
    }
    __syncthreads();

    if (svalid) {
        const int s = ss, e = se;
        const float4* base = (const float4*)emb + (size_t)b * S_ * H4_ + tid;

        float4 a0 = {0,0,0,0}, a1 = {0,0,0,0}, a2 = {0,0,0,0}, a3 = {0,0,0,0};
        int t = s;
        for (; t + 3 < e; t += 4) {
            f4add(a0, base[(size_t)(t + 0) * H4_]);
            f4add(a1, base[(size_t)(t + 1) * H4_]);
            f4add(a2, base[(size_t)(t + 2) * H4_]);
            f4add(a3, base[(size_t)(t + 3) * H4_]);
        }
        for (; t < e; t++) f4add(a0, base[(size_t)t * H4_]);
        f4add(a0, a1); f4add(a2, a3); f4add(a0, a2);

        float* dst = g_pooled + b * H_ + tid * 4;
        atomicAdd(dst + 0, a0.x);
        atomicAdd(dst + 1, a0.y);
        atomicAdd(dst + 2, a0.z);
        atomicAdd(dst + 3, a0.w);
    }

    // ---------------- Ticket 1 ----------------------------------------------
    __threadfence();
    __syncthreads();
    if (tid == 0) s_ticket = atomicAdd(&g_cnt1, 1u);
    __syncthreads();
    const unsigned ticket = s_ticket;
    if (ticket < (unsigned)(NBLK_ - NFC1_)) return;

    if (tid == 0) {
        volatile unsigned* p = &g_cnt1;
        while (*p < (unsigned)NBLK_) { }
    }
    __syncthreads();
    __threadfence();

    // ---------------- Phase 2: fc1 + fc2 partial ----------------------------
    const unsigned tile = ticket - (unsigned)(NBLK_ - NFC1_);
    const int bg = (int)(tile & 3u);          // b-group of 8 rows
    const int jt = (int)(tile >> 2);          // j-tile of 32 cols
    const int lane = tid & 31;
    const int ty = tid >> 5;                  // 0..7
    const int j = jt * 32 + lane;
    const int brow = bg * 8 + ty;

    if (tid < 8) {
        const int* row = spans + (bg * 8 + tid) * (NSPANS_ * 2);
        int total = 0;
        #pragma unroll
        for (int m = 0; m < NSPANS_; m++) {
            int a = row[2 * m], e = row[2 * m + 1];
            if (a == 0 && e == 0) break;
            total += e - a;
        }
        s_inv[tid] = 1.0f / (float)total;
    }

    // tile-fetch geometry
    const int wrow = tid >> 3;                // 0..31
    const int wcol = (tid & 7) * 4;           // float4 column
    const float* wptr = W1 + (size_t)wrow * H_ + jt * 32 + wcol;
    const int prow = tid >> 5;                // 0..7
    const int pcol = tid & 31;
    const float* pptr = g_pooled + (bg * 8 + prow) * H_ + pcol;

    // prologue: tile 0
    float4 rw = *(const float4*)(wptr);
    float rp = pptr[0];
    *(float4*)&wt[0][wrow][wcol] = rw;
    pt[0][prow][pcol] = rp;
    __syncthreads();

    float c0 = 0.f, c1 = 0.f, c2 = 0.f, c3 = 0.f;

    #pragma unroll 1
    for (int t = 0; t < H_ / KT_; t++) {
        if (t + 1 < H_ / KT_) {
            rw = *(const float4*)(wptr + (size_t)(t + 1) * KT_ * H_);
            rp = pptr[(t + 1) * KT_];
        }

        const float* wk = &wt[t & 1][0][lane];
        const float* pk = &pt[t & 1][ty][0];
        #pragma unroll
        for (int k = 0; k < KT_; k += 4) {
            c0 += pk[k + 0] * wk[(k + 0) * 32];
            c1 += pk[k + 1] * wk[(k + 1) * 32];
            c2 += pk[k + 2] * wk[(k + 2) * 32];
            c3 += pk[k + 3] * wk[(k + 3) * 32];
        }

        if (t + 1 < H_ / KT_) {
            *(float4*)&wt[(t + 1) & 1][wrow][wcol] = rw;
            pt[(t + 1) & 1][prow][pcol] = rp;
        }
        __syncthreads();
    }
    const float dot = (c0 + c1) + (c2 + c3);
    const float h = fmaxf(fmaf(dot, s_inv[ty], b1[j]), 0.f);

    // fc2 partial: broadcast each lane's h; lane c accumulates class c
    float accc = 0.f;
    const int jbase = jt * 32;
    #pragma unroll
    for (int l = 0; l < 32; l++) {
        const float hv = __shfl_sync(0xffffffffu, h, l);
        if (lane < NCLS_)
            accc += hv * W2[(jbase + l) * NCLS_ + lane];
    }
    if (lane < NCLS_)
        atomicAdd(g_logits + brow * NCLS_ + lane, accc);

    // ---------------- Ticket 2: last block runs the epilogue ----------------
    __threadfence();
    __syncthreads();
    if (tid == 0) s_ticket2 = atomicAdd(&g_cnt2, 1u);
    __syncthreads();
    if (s_ticket2 != (unsigned)(NFC1_ - 1)) return;
    __threadfence();

    // ---------------- Phase 3: sigmoid + restore zero state -----------------
    for (int idx = tid; idx < B_ * NCLS_; idx += 256) {
        const float v = __ldcg(g_logits + idx) + b2[idx % NCLS_];
        out[idx] = 1.f / (1.f + __expf(-v));
        g_logits[idx] = 0.f;
    }
    {
        float4* pz = (float4*)g_pooled;
        for (int k = tid; k < B_ * H4_; k += 256)
            pz[k] = make_float4(0.f, 0.f, 0.f, 0.f);
    }
    if (tid == 0) { g_cnt1 = 0u; g_cnt2 = 0u; }
}

// ---------------------------------------------------------------------------
extern "C" void kernel_launch(void* const* d_in, const int* in_sizes, int n_in,
                              void* d_out, int out_size) {
    const float* all_emb = (const float*)d_in[0];
    const int*   spans   = (const int*)d_in[1];
    const float* W1      = (const float*)d_in[2];
    const float* b1      = (const float*)d_in[3];
    const float* W2      = (const float*)d_in[4];
    const float* b2      = (const float*)d_in[5];
    float* out = (float*)d_out;

    dim3 grid(NCHUNK_, NSPANS_, B_);
    fused_kernel<<<grid, 256>>>(all_emb, spans, W1, b1, W2, b2, out);
}

// round 8
// speedup vs baseline: 2.2444x; 2.2444x over previous
#include <cuda_runtime.h>

#define B_ 32
#define S_ 4096
#define H_ 1024
#define NSPANS_ 16
#define NCLS_ 25
#define H4_ (H_ / 4)      // 256 float4 per row
#define CHUNK_ 16         // tokens per pool block
#define NCHUNK_ 4         // ceil(63 / CHUNK_)
#define NFC1_ 128         // fc1 tiles (32 j-tiles x 4 b-groups)
#define KT_ 32            // K-tile rows in fc1
#define KHALF_ (H_ / 2)   // 512

// Persistent scratch. Zero-initialized at load; the fc1 epilogue restores
// zeros at the end of every call, so each invocation sees identical state.
__device__ float g_pooled[B_ * H_];
__device__ float g_logits[B_ * NCLS_];
__device__ unsigned g_cnt;

__device__ __forceinline__ void f4add(float4& a, const float4 b) {
    a.x += b.x; a.y += b.y; a.z += b.z; a.w += b.w;
}

// ---------------------------------------------------------------------------
// Kernel 1: span gather-sum. grid (NCHUNK, NSPANS, B), block 256, tiny smem.
// (unchanged from round-6 winner)
// ---------------------------------------------------------------------------
__global__ void __launch_bounds__(256)
pool_kernel(const float* __restrict__ emb,
            const int* __restrict__ spans,
            float* __restrict__ pooled) {
    const int b = blockIdx.z;
    const int n = blockIdx.y;
    const int c = blockIdx.x;

    __shared__ int ss, se, svalid;
    if (threadIdx.x == 0) {
        const int* row = spans + b * (NSPANS_ * 2);
        int s = row[2 * n], e = row[2 * n + 1];
        int v = !(s == 0 && e == 0);
        for (int m = 0; m < n && v; m++) {           // torch 'break' semantics
            if (row[2 * m] == 0 && row[2 * m + 1] == 0) v = 0;
        }
        int cs = s + c * CHUNK_;
        int ce = cs + CHUNK_ < e ? cs + CHUNK_ : e;
        ss = cs; se = ce; svalid = v && (cs < e);
    }
    __syncthreads();
    if (!svalid) return;

    const int s = ss, e = se;
    const float4* base = (const float4*)emb + (size_t)b * S_ * H4_ + threadIdx.x;

    float4 a0 = {0,0,0,0}, a1 = {0,0,0,0}, a2 = {0,0,0,0}, a3 = {0,0,0,0};
    int t = s;
    for (; t + 3 < e; t += 4) {
        f4add(a0, base[(size_t)(t + 0) * H4_]);
        f4add(a1, base[(size_t)(t + 1) * H4_]);
        f4add(a2, base[(size_t)(t + 2) * H4_]);
        f4add(a3, base[(size_t)(t + 3) * H4_]);
    }
    for (; t < e; t++) f4add(a0, base[(size_t)t * H4_]);
    f4add(a0, a1); f4add(a2, a3); f4add(a0, a2);

    float* dst = pooled + b * H_ + threadIdx.x * 4;
    atomicAdd(dst + 0, a0.x);
    atomicAdd(dst + 1, a0.y);
    atomicAdd(dst + 2, a0.z);
    atomicAdd(dst + 3, a0.w);
}

// ---------------------------------------------------------------------------
// Kernel 2: fc1 (register-blocked: 1 j x 2 batches x 512 k per thread, split-K
// closed via smem) + fc2-partial + last-ticket sigmoid epilogue.
// grid 128 (tile: bg = tile&3, jt = tile>>2), block 256 threads:
//   lane = j within 32-wide tile; ty = (batch-pair bp = ty>>1, k-half kh = ty&1).
// ---------------------------------------------------------------------------
__global__ void __launch_bounds__(256)
fc1_kernel(const int* __restrict__ spans,
           const float* __restrict__ W1,
           const float* __restrict__ b1,
           const float* __restrict__ W2,
           const float* __restrict__ b2,
           float* __restrict__ out) {
    const int tile = blockIdx.x;
    const int bg = tile & 3;
    const int jt = tile >> 2;
    const int tid = threadIdx.x;
    const int lane = tid & 31;
    const int ty = tid >> 5;          // 0..7
    const int kh = ty & 1;            // k-half
    const int bp = ty >> 1;           // batch-pair 0..3
    const int j = jt * 32 + lane;

    __shared__ float sp[8][H_];              // 32 KB pooled/count rows
    __shared__ float wt[2][2][KT_][32];      // 16 KB dual double-buffered tiles
    __shared__ float redA[4][32], redB[4][32];
    __shared__ float s_inv[8];
    __shared__ unsigned s_ticket;

    if (tid < 8) {
        const int* row = spans + (bg * 8 + tid) * (NSPANS_ * 2);
        int total = 0;
        #pragma unroll
        for (int m = 0; m < NSPANS_; m++) {
            int a = row[2 * m], e = row[2 * m + 1];
            if (a == 0 && e == 0) break;
            total += e - a;
        }
        s_inv[tid] = 1.0f / (float)total;
    }
    __syncthreads();

    // stage pooled/total into smem (float4)
    {
        const float4* psrc = (const float4*)(g_pooled + bg * 8 * H_);
        float4* pdst = (float4*)&sp[0][0];
        for (int k = tid; k < 8 * H4_; k += 256) {
            float4 v = psrc[k];
            const float inv = s_inv[k >> 8];
            v.x *= inv; v.y *= inv; v.z *= inv; v.w *= inv;
            pdst[k] = v;
        }
    }

    // W1 tile fetch geometry: per iter fetch BOTH k-half tiles (2 float4/thr)
    const int wrow = tid >> 3;           // 0..31 (k within tile)
    const int wcol = (tid & 7) * 4;      // float4 j-column
    const float* wptr0 = W1 + (size_t)wrow * H_ + jt * 32 + wcol;
    const float* wptr1 = W1 + (size_t)(KHALF_ + wrow) * H_ + jt * 32 + wcol;

    float4 r0 = *(const float4*)(wptr0);
    float4 r1 = *(const float4*)(wptr1);
    *(float4*)&wt[0][0][wrow][wcol] = r0;
    *(float4*)&wt[0][1][wrow][wcol] = r1;
    __syncthreads();

    const float* pa_base = &sp[2 * bp + 0][kh * KHALF_];
    const float* pb_base = &sp[2 * bp + 1][kh * KHALF_];

    float a0 = 0.f, a1 = 0.f, ba = 0.f, bb = 0.f;

    #pragma unroll 1
    for (int t = 0; t < KHALF_ / KT_; t++) {     // 16 iters
        if (t + 1 < KHALF_ / KT_) {
            r0 = *(const float4*)(wptr0 + (size_t)(t + 1) * KT_ * H_);
            r1 = *(const float4*)(wptr1 + (size_t)(t + 1) * KT_ * H_);
        }

        const float* wk = &wt[t & 1][kh][0][lane];
        const float4* pa = (const float4*)(pa_base + t * KT_);
        const float4* pb = (const float4*)(pb_base + t * KT_);
        #pragma unroll
        for (int kk = 0; kk < 8; kk++) {
            const float4 x = pa[kk];
            const float4 y = pb[kk];
            const float w0 = wk[(4 * kk + 0) * 32];
            const float w1 = wk[(4 * kk + 1) * 32];
            const float w2 = wk[(4 * kk + 2) * 32];
            const float w3 = wk[(4 * kk + 3) * 32];
            a0 = fmaf(x.x, w0, a0); a1 = fmaf(x.y, w1, a1);
            ba = fmaf(y.x, w0, ba); bb = fmaf(y.y, w1, bb);
            a0 = fmaf(x.z, w2, a0); a1 = fmaf(x.w, w3, a1);
            ba = fmaf(y.z, w2, ba); bb = fmaf(y.w, w3, bb);
        }

        if (t + 1 < KHALF_ / KT_) {
            *(float4*)&wt[(t + 1) & 1][0][wrow][wcol] = r0;
            *(float4*)&wt[(t + 1) & 1][1][wrow][wcol] = r1;
        }
        __syncthreads();
    }
    float d0 = a0 + a1;    // batch 2bp   partial (this k-half)
    float d1 = ba + bb;    // batch 2bp+1 partial

    // close split-K: kh==1 publishes, kh==0 reduces + does epilogue math
    if (kh == 1) { redA[bp][lane] = d0; redB[bp][lane] = d1; }
    __syncthreads();
    if (kh == 0) {
        d0 += redA[bp][lane];
        d1 += redB[bp][lane];
        const float bias = b1[j];
        const float h0 = fmaxf(d0 + bias, 0.f);
        const float h1 = fmaxf(d1 + bias, 0.f);

        // fc2 partial for 2 batches
        float acc0 = 0.f, acc1 = 0.f;
        const int jbase = jt * 32;
        #pragma unroll
        for (int l = 0; l < 32; l++) {
            const float hv0 = __shfl_sync(0xffffffffu, h0, l);
            const float hv1 = __shfl_sync(0xffffffffu, h1, l);
            if (lane < NCLS_) {
                const float wv = W2[(jbase + l) * NCLS_ + lane];
                acc0 = fmaf(hv0, wv, acc0);
                acc1 = fmaf(hv1, wv, acc1);
            }
        }
        if (lane < NCLS_) {
            const int brow0 = bg * 8 + 2 * bp;
            atomicAdd(g_logits + brow0 * NCLS_ + lane, acc0);
            atomicAdd(g_logits + (brow0 + 1) * NCLS_ + lane, acc1);
        }
    }

    // ---- ticket: the block drawing NFC1_-1 is provably last; no spin -------
    __threadfence();
    __syncthreads();
    if (tid == 0) s_ticket = atomicAdd(&g_cnt, 1u);
    __syncthreads();
    if (s_ticket != (unsigned)(NFC1_ - 1)) return;

    // ---- epilogue: sigmoid + restore zero state -----------------------------
    for (int idx = tid; idx < B_ * NCLS_; idx += 256) {
        const float v = __ldcg(g_logits + idx) + b2[idx % NCLS_];
        out[idx] = 1.f / (1.f + __expf(-v));
        g_logits[idx] = 0.f;
    }
    {
        float4* pz = (float4*)g_pooled;
        for (int k = tid; k < B_ * H4_; k += 256)
            pz[k] = make_float4(0.f, 0.f, 0.f, 0.f);
    }
    if (tid == 0) g_cnt = 0u;
}

// ---------------------------------------------------------------------------
extern "C" void kernel_launch(void* const* d_in, const int* in_sizes, int n_in,
                              void* d_out, int out_size) {
    const float* all_emb = (const float*)d_in[0];
    const int*   spans   = (const int*)d_in[1];
    const float* W1      = (const float*)d_in[2];
    const float* b1      = (const float*)d_in[3];
    const float* W2      = (const float*)d_in[4];
    const float* b2      = (const float*)d_in[5];
    float* out = (float*)d_out;

    float* pooled;
    cudaGetSymbolAddress((void**)&pooled, g_pooled);

    {
        dim3 grid(NCHUNK_, NSPANS_, B_);
        pool_kernel<<<grid, 256>>>(all_emb, spans, pooled);
    }
    fc1_kernel<<<NFC1_, 256>>>(spans, W1, b1, W2, b2, out);
}

// round 9
// speedup vs baseline: 2.4247x; 1.0804x over previous
#include <cuda_runtime.h>

#define B_ 32
#define S_ 4096
#define H_ 1024
#define NSPANS_ 16
#define NCLS_ 25
#define H4_ (H_ / 4)      // 256 float4 per row
#define CHUNK_ 16         // tokens per pool block
#define NCHUNK_ 4         // ceil(63 / CHUNK_)
#define NFC1_ 128         // fc1 tiles (32 j-tiles x 4 b-groups)
#define KT_ 32            // K-tile rows per quarter per iteration
#define KQLEN_ (H_ / 4)   // 256 k-rows per quarter
#define NIT_ (KQLEN_ / KT_)  // 8 iterations

// Persistent scratch. Zero-initialized at load; the fc1 epilogue restores
// zeros at the end of every call, so each invocation sees identical state.
__device__ float g_pooled[B_ * H_];
__device__ float g_logits[B_ * NCLS_];
__device__ unsigned g_cnt;

__device__ __forceinline__ void f4add(float4& a, const float4 b) {
    a.x += b.x; a.y += b.y; a.z += b.z; a.w += b.w;
}

// ---------------------------------------------------------------------------
// Kernel 1: span gather-sum. grid (NCHUNK, NSPANS, B), block 256, tiny smem.
// (unchanged from round-6/8 winner)
// ---------------------------------------------------------------------------
__global__ void __launch_bounds__(256)
pool_kernel(const float* __restrict__ emb,
            const int* __restrict__ spans,
            float* __restrict__ pooled) {
    const int b = blockIdx.z;
    const int n = blockIdx.y;
    const int c = blockIdx.x;

    __shared__ int ss, se, svalid;
    if (threadIdx.x == 0) {
        const int* row = spans + b * (NSPANS_ * 2);
        int s = row[2 * n], e = row[2 * n + 1];
        int v = !(s == 0 && e == 0);
        for (int m = 0; m < n && v; m++) {           // torch 'break' semantics
            if (row[2 * m] == 0 && row[2 * m + 1] == 0) v = 0;
        }
        int cs = s + c * CHUNK_;
        int ce = cs + CHUNK_ < e ? cs + CHUNK_ : e;
        ss = cs; se = ce; svalid = v && (cs < e);
    }
    __syncthreads();
    if (!svalid) return;

    const int s = ss, e = se;
    const float4* base = (const float4*)emb + (size_t)b * S_ * H4_ + threadIdx.x;

    float4 a0 = {0,0,0,0}, a1 = {0,0,0,0}, a2 = {0,0,0,0}, a3 = {0,0,0,0};
    int t = s;
    for (; t + 3 < e; t += 4) {
        f4add(a0, base[(size_t)(t + 0) * H4_]);
        f4add(a1, base[(size_t)(t + 1) * H4_]);
        f4add(a2, base[(size_t)(t + 2) * H4_]);
        f4add(a3, base[(size_t)(t + 3) * H4_]);
    }
    for (; t < e; t++) f4add(a0, base[(size_t)t * H4_]);
    f4add(a0, a1); f4add(a2, a3); f4add(a0, a2);

    float* dst = pooled + b * H_ + threadIdx.x * 4;
    atomicAdd(dst + 0, a0.x);
    atomicAdd(dst + 1, a0.y);
    atomicAdd(dst + 2, a0.z);
    atomicAdd(dst + 3, a0.w);
}

// ---------------------------------------------------------------------------
// Kernel 2: fc1, 512 threads, 4-way split-K.
// grid 128 (tile: bg = tile&3 b-group of 8, jt = tile>>2 j-tile of 32).
// Warp ty=tid>>5: kq = ty&3 (k-quarter of 256), bp = ty>>2 (batch pair).
// Per iteration both W1 (4x32x32) and pooled (4x8x32) tiles are cooperatively
// fetched double-buffered; split-K closed in smem; kq==0 warps run relu +
// fc2-partial; last-ticket block runs sigmoid epilogue + re-zeroes state.
// ---------------------------------------------------------------------------
__global__ void __launch_bounds__(512)
fc1_kernel(const int* __restrict__ spans,
           const float* __restrict__ W1,
           const float* __restrict__ b1,
           const float* __restrict__ W2,
           const float* __restrict__ b2,
           float* __restrict__ out) {
    const int tile = blockIdx.x;
    const int bg = tile & 3;
    const int jt = tile >> 2;
    const int tid = threadIdx.x;
    const int lane = tid & 31;
    const int ty = tid >> 5;          // 0..15
    const int kq = ty & 3;            // k-quarter
    const int bp = ty >> 2;           // batch-pair 0..3
    const int j = jt * 32 + lane;

    __shared__ float wt[2][4][KT_][32];   // 32 KB W1 tiles (per quarter)
    __shared__ float pt[2][4][8][KT_];    // 8 KB pooled tiles (per quarter)
    __shared__ float redA[3][4][32], redB[3][4][32];  // 3 KB split-K exchange
    __shared__ float s_inv[8];
    __shared__ unsigned s_ticket;

    if (tid < 8) {
        const int* row = spans + (bg * 8 + tid) * (NSPANS_ * 2);
        int total = 0;
        #pragma unroll
        for (int m = 0; m < NSPANS_; m++) {
            int a = row[2 * m], e = row[2 * m + 1];
            if (a == 0 && e == 0) break;
            total += e - a;
        }
        s_inv[tid] = 1.0f / (float)total;
    }

    // --- cooperative fetch geometry ---
    // W1: 4 quarters x 32 rows x 8 float4-cols = 1024 float4; 2 per thread.
    const int wq = tid >> 7;                   // quarter 0..3
    const int wr = (tid & 127) >> 2;           // k-row within tile 0..31
    const int wc = (tid & 3) * 8;              // float-col 0,8,16,24
    const float* wsrc =
        W1 + (size_t)(wq * KQLEN_ + wr) * H_ + jt * 32 + wc;
    // pooled: 4 quarters x 8 rows x 8 float4 = 256 float4; tid<256, 1 each.
    const int pq = (tid >> 6) & 3;
    const int pr = (tid >> 3) & 7;
    const int pc = (tid & 7) * 4;
    const float* psrc =
        g_pooled + (size_t)(bg * 8 + pr) * H_ + pq * KQLEN_ + pc;

    // prologue: tile 0
    float4 rw0 = *(const float4*)(wsrc);
    float4 rw1 = *(const float4*)(wsrc + 4);
    float4 rp;
    if (tid < 256) rp = *(const float4*)(psrc);
    *(float4*)&wt[0][wq][wr][wc] = rw0;
    *(float4*)&wt[0][wq][wr][wc + 4] = rw1;
    if (tid < 256) *(float4*)&pt[0][pq][pr][pc] = rp;
    __syncthreads();

    float a0 = 0.f, a1 = 0.f, ba = 0.f, bb = 0.f;

    #pragma unroll 1
    for (int t = 0; t < NIT_; t++) {
        if (t + 1 < NIT_) {
            rw0 = *(const float4*)(wsrc + (size_t)(t + 1) * KT_ * H_);
            rw1 = *(const float4*)(wsrc + (size_t)(t + 1) * KT_ * H_ + 4);
            if (tid < 256) rp = *(const float4*)(psrc + (t + 1) * KT_);
        }

        const float* wk = &wt[t & 1][kq][0][lane];
        const float4* pa = (const float4*)&pt[t & 1][kq][2 * bp + 0][0];
        const float4* pb = (const float4*)&pt[t & 1][kq][2 * bp + 1][0];
        #pragma unroll
        for (int kk = 0; kk < 8; kk++) {
            const float4 x = pa[kk];
            const float4 y = pb[kk];
            const float w0 = wk[(4 * kk + 0) * 32];
            const float w1 = wk[(4 * kk + 1) * 32];
            const float w2 = wk[(4 * kk + 2) * 32];
            const float w3 = wk[(4 * kk + 3) * 32];
            a0 = fmaf(x.x, w0, a0); a1 = fmaf(x.y, w1, a1);
            ba = fmaf(y.x, w0, ba); bb = fmaf(y.y, w1, bb);
            a0 = fmaf(x.z, w2, a0); a1 = fmaf(x.w, w3, a1);
            ba = fmaf(y.z, w2, ba); bb = fmaf(y.w, w3, bb);
        }

        if (t + 1 < NIT_) {
            *(float4*)&wt[(t + 1) & 1][wq][wr][wc] = rw0;
            *(float4*)&wt[(t + 1) & 1][wq][wr][wc + 4] = rw1;
            if (tid < 256) *(float4*)&pt[(t + 1) & 1][pq][pr][pc] = rp;
        }
        __syncthreads();
    }
    float d0 = a0 + a1;    // batch 2bp   partial (this quarter)
    float d1 = ba + bb;    // batch 2bp+1 partial

    // close split-K
    if (kq != 0) {
        redA[kq - 1][bp][lane] = d0;
        redB[kq - 1][bp][lane] = d1;
    }
    __syncthreads();
    if (kq == 0) {
        d0 += redA[0][bp][lane] + redA[1][bp][lane] + redA[2][bp][lane];
        d1 += redB[0][bp][lane] + redB[1][bp][lane] + redB[2][bp][lane];
        const float bias = b1[j];
        const float h0 = fmaxf(fmaf(d0, s_inv[2 * bp + 0], bias), 0.f);
        const float h1 = fmaxf(fmaf(d1, s_inv[2 * bp + 1], bias), 0.f);

        // fc2 partial for 2 batches
        float acc0 = 0.f, acc1 = 0.f;
        const int jbase = jt * 32;
        #pragma unroll
        for (int l = 0; l < 32; l++) {
            const float hv0 = __shfl_sync(0xffffffffu, h0, l);
            const float hv1 = __shfl_sync(0xffffffffu, h1, l);
            if (lane < NCLS_) {
                const float wv = W2[(jbase + l) * NCLS_ + lane];
                acc0 = fmaf(hv0, wv, acc0);
                acc1 = fmaf(hv1, wv, acc1);
            }
        }
        if (lane < NCLS_) {
            const int brow0 = bg * 8 + 2 * bp;
            atomicAdd(g_logits + brow0 * NCLS_ + lane, acc0);
            atomicAdd(g_logits + (brow0 + 1) * NCLS_ + lane, acc1);
        }
    }

    // ---- ticket: the block drawing NFC1_-1 is provably last; no spin -------
    __threadfence();
    __syncthreads();
    if (tid == 0) s_ticket = atomicAdd(&g_cnt, 1u);
    __syncthreads();
    if (s_ticket != (unsigned)(NFC1_ - 1)) return;

    // ---- epilogue: sigmoid + restore zero state -----------------------------
    for (int idx = tid; idx < B_ * NCLS_; idx += 512) {
        const float v = __ldcg(g_logits + idx) + b2[idx % NCLS_];
        out[idx] = 1.f / (1.f + __expf(-v));
        g_logits[idx] = 0.f;
    }
    {
        float4* pz = (float4*)g_pooled;
        for (int k = tid; k < B_ * H4_; k += 512)
            pz[k] = make_float4(0.f, 0.f, 0.f, 0.f);
    }
    if (tid == 0) g_cnt = 0u;
}

// ---------------------------------------------------------------------------
extern "C" void kernel_launch(void* const* d_in, const int* in_sizes, int n_in,
                              void* d_out, int out_size) {
    const float* all_emb = (const float*)d_in[0];
    const int*   spans   = (const int*)d_in[1];
    const float* W1      = (const float*)d_in[2];
    const float* b1      = (const float*)d_in[3];
    const float* W2      = (const float*)d_in[4];
    const float* b2      = (const float*)d_in[5];
    float* out = (float*)d_out;

    float* pooled;
    cudaGetSymbolAddress((void**)&pooled, g_pooled);

    {
        dim3 grid(NCHUNK_, NSPANS_, B_);
        pool_kernel<<<grid, 256>>>(all_emb, spans, pooled);
    }
    fc1_kernel<<<NFC1_, 512>>>(spans, W1, b1, W2, b2, out);
}